// round 8
// baseline (speedup 1.0000x reference)
#include <cuda_runtime.h>

// Problem constants
#define NB 8
#define NT 4096
#define ND 2048
#define NS 64
#define M_TOT (NB*NT)      // 32768 rows
#define N_CAT (2*NS)       // 128 (Wa rows ++ Wb rows)
#define NCHUNK 64          // scan chunks
#define CLEN   64          // steps per chunk (NCHUNK*CLEN == NT)

// ---------------- scratch (static __device__ — no allocations allowed) ----
__device__ float        g_a[(size_t)M_TOT*NS];        // 8 MB  gate  (fp32)
__device__ float        g_b[(size_t)M_TOT*NS];        // 8 MB  input (fp32)
__device__ unsigned int g_hs[(size_t)M_TOT*NS];       // 8 MB  states (tf32 bits)
__device__ unsigned int g_Wcat[(size_t)N_CAT*ND];     // 1 MB  [n][k] tf32
__device__ unsigned int g_Wo[(size_t)ND*NS];          // 512KB [d][s] tf32
__device__ float        g_A[(size_t)NB*NCHUNK*NS];    // chunk gate products
__device__ float        g_E[(size_t)NB*NCHUNK*NS];    // chunk local end values
__device__ float        g_hin[(size_t)NB*NCHUNK*NS];  // chunk entry states

// ---------------- helpers -------------------------------------------------
__device__ __forceinline__ unsigned int f2tf(float f) {
    unsigned int u;
    asm("cvt.rna.tf32.f32 %0, %1;" : "=r"(u) : "f"(f));
    return u;
}

__device__ __forceinline__ void mma8(float c[4], const unsigned int a[4],
                                     const unsigned int b[2]) {
    asm volatile(
        "mma.sync.aligned.m16n8k8.row.col.f32.tf32.tf32.f32 "
        "{%0,%1,%2,%3},{%4,%5,%6,%7},{%8,%9},{%0,%1,%2,%3};"
        : "+f"(c[0]), "+f"(c[1]), "+f"(c[2]), "+f"(c[3])
        : "r"(a[0]), "r"(a[1]), "r"(a[2]), "r"(a[3]), "r"(b[0]), "r"(b[1]));
}

__device__ __forceinline__ void cpa16(void* sdst, const void* gsrc) {
    unsigned int sa = (unsigned int)__cvta_generic_to_shared(sdst);
    asm volatile("cp.async.cg.shared.global [%0], [%1], 16;"
                 :: "r"(sa), "l"(gsrc) : "memory");
}
__device__ __forceinline__ void cp_commit() {
    asm volatile("cp.async.commit_group;" ::: "memory");
}

// ---------------- kernel 0: weight pre-conversion to tf32 -----------------
__global__ void __launch_bounds__(256)
prep_kernel(const float* __restrict__ Wa, const float* __restrict__ Wb,
            const float* __restrict__ Wout) {
    int i = blockIdx.x * 256 + threadIdx.x;
    const int n_cat = N_CAT * ND;           // 262144
    const int n_wo  = ND * NS;              // 131072
    if (i < n_cat) {
        int n = i / ND, k = i - n * ND;
        float v = (n < NS) ? Wa[n*ND + k] : Wb[(n-NS)*ND + k];
        g_Wcat[i] = f2tf(v);
    } else if (i < n_cat + n_wo) {
        int j = i - n_cat;
        g_Wo[j] = f2tf(Wout[j]);
    }
}

// ---------------- kernel 1: a,b = tanh(x @ Wcat^T + bias) -----------------
// GEMM M=32768, N=128, K=2048. 128x128 blocks, BK=32, THREE-stage cp.async
// pipeline (2 prefetch stages in flight >= DRAM latency).
// 16 warps in 4(m) x 4(n) grid, each warp 32x32 via m16n8k8 tf32 mma.
#define BK1  32
#define LDA1 36   // padded smem stride (36 mod 32 = 4 -> conflict-free frags)
#define NSTG 3

__global__ void __launch_bounds__(512, 2)
proj_kernel(const float* __restrict__ x, const float* __restrict__ ba,
            const float* __restrict__ bb) {
    extern __shared__ char sm[];
    float*        Xs   = (float*)sm;                               // [3][128][LDA1]
    unsigned int* Ws   = (unsigned int*)(sm + NSTG*128*LDA1*4);    // [3][128][LDA1]
    float*        bias = (float*)(sm + 2*NSTG*128*LDA1*4);         // [128]

    const int tid  = threadIdx.x;
    const int warp = tid >> 5, lane = tid & 31;
    const int g  = lane >> 2, t4 = lane & 3;
    const int wm = warp >> 2, wn = warp & 3;   // 4m x 4n, warp tile 32x32
    const int m0 = blockIdx.x * 128;

    if (tid < 128) bias[tid] = (tid < NS) ? ba[tid] : bb[tid - NS];

    float acc[2][4][4];
    #pragma unroll
    for (int i = 0; i < 2; i++)
        #pragma unroll
        for (int j = 0; j < 4; j++)
            #pragma unroll
            for (int k = 0; k < 4; k++) acc[i][j][k] = 0.f;

    auto issue = [&](int buf, int k0) {
        #pragma unroll
        for (int j = 0; j < 2; j++) {
            int c   = tid + j * 512;       // 1024 chunks of 4 floats
            int row = c >> 3;              // 8 chunks per 32-wide row
            int kc  = (c & 7) * 4;
            cpa16(&Xs[(buf*128 + row)*LDA1 + kc],
                  &x[(size_t)(m0 + row)*ND + k0 + kc]);
            cpa16(&Ws[(buf*128 + row)*LDA1 + kc],
                  &g_Wcat[(size_t)row*ND + k0 + kc]);
        }
        cp_commit();
    };

    const int KT = ND / BK1;   // 64
    issue(0, 0);
    issue(1, BK1);
    for (int kt = 0; kt < KT; kt++) {
        const int cur = kt % NSTG;
        if (kt + 2 < KT) {
            issue((kt + 2) % NSTG, (kt + 2) * BK1);
            asm volatile("cp.async.wait_group 2;" ::: "memory");
        } else if (kt + 1 < KT) {
            asm volatile("cp.async.wait_group 1;" ::: "memory");
        } else {
            asm volatile("cp.async.wait_group 0;" ::: "memory");
        }
        __syncthreads();

        const float*        Xc = &Xs[cur * 128 * LDA1];
        const unsigned int* Wc = &Ws[cur * 128 * LDA1];
        #pragma unroll
        for (int kk = 0; kk < 4; kk++) {
            unsigned int af[2][4];
            #pragma unroll
            for (int im = 0; im < 2; im++) {
                int r = wm*32 + im*16 + g;
                int c = kk*8 + t4;
                // raw fp32 bits: tensor core truncates mantissa to tf32
                af[im][0] = __float_as_uint(Xc[r*LDA1 + c]);
                af[im][1] = __float_as_uint(Xc[(r+8)*LDA1 + c]);
                af[im][2] = __float_as_uint(Xc[r*LDA1 + c + 4]);
                af[im][3] = __float_as_uint(Xc[(r+8)*LDA1 + c + 4]);
            }
            unsigned int bf[4][2];
            #pragma unroll
            for (int in = 0; in < 4; in++) {
                int n = wn*32 + in*8 + g;
                int c = kk*8 + t4;
                bf[in][0] = Wc[n*LDA1 + c];
                bf[in][1] = Wc[n*LDA1 + c + 4];
            }
            #pragma unroll
            for (int im = 0; im < 2; im++)
                #pragma unroll
                for (int in = 0; in < 4; in++)
                    mma8(acc[im][in], af[im], bf[in]);
        }
        __syncthreads();
    }

    // Epilogue: + bias, tanh, split store to g_a (cols<64) / g_b (cols>=64)
    float* dst = (wn >= 2) ? g_b : g_a;
    #pragma unroll
    for (int im = 0; im < 2; im++) {
        #pragma unroll
        for (int in = 0; in < 4; in++) {
            int ncol = wn*32 + in*8 + 2*t4;       // global col 0..127
            float b0v = bias[ncol], b1v = bias[ncol + 1];
            int cl = (wn & 1)*32 + in*8 + 2*t4;   // local col within 64
            size_t r0 = (size_t)(m0 + wm*32 + im*16 + g);
            float2 v0 = make_float2(tanhf(acc[im][in][0] + b0v),
                                    tanhf(acc[im][in][1] + b1v));
            float2 v1 = make_float2(tanhf(acc[im][in][2] + b0v),
                                    tanhf(acc[im][in][3] + b1v));
            *(float2*)&dst[r0*NS + cl]       = v0;
            *(float2*)&dst[(r0+8)*NS + cl]   = v1;
        }
    }
}

// ---------------- kernel 2: chunked affine scan over T --------------------
// Pass 1: per (batch, chunk, state): A = prod(a), E = local scan end (h_in=0)
// 256-thread blocks, each thread owns 4 states (float4), 16 chunks per block.
__global__ void __launch_bounds__(256)
scan1_kernel() {
    const int t  = threadIdx.x;
    const int c  = blockIdx.x * 16 + (t >> 4);   // chunk 0..63
    const int b  = blockIdx.y;
    const int s  = (t & 15) * 4;
    size_t base = ((size_t)b * NT + (size_t)c * CLEN) * NS + s;
    float4 A = make_float4(1.f, 1.f, 1.f, 1.f);
    float4 E = make_float4(0.f, 0.f, 0.f, 0.f);
    #pragma unroll 8
    for (int tt = 0; tt < CLEN; tt++) {
        float4 av = *(const float4*)&g_a[base + (size_t)tt * NS];
        float4 bv = *(const float4*)&g_b[base + (size_t)tt * NS];
        E.x = fmaf(av.x, E.x, bv.x); A.x *= av.x;
        E.y = fmaf(av.y, E.y, bv.y); A.y *= av.y;
        E.z = fmaf(av.z, E.z, bv.z); A.z *= av.z;
        E.w = fmaf(av.w, E.w, bv.w); A.w *= av.w;
    }
    int o = (b * NCHUNK + c) * NS + s;
    *(float4*)&g_A[o] = A;
    *(float4*)&g_E[o] = E;
}

// Pass 2: sequential combine across chunks, staged through shared memory.
__global__ void __launch_bounds__(64)
scan2_kernel() {
    __shared__ float As[NCHUNK][NS];
    __shared__ float Es[NCHUNK][NS];
    const int b = blockIdx.x, s = threadIdx.x;

    #pragma unroll
    for (int c = 0; c < NCHUNK; c++) {
        int o = (b * NCHUNK + c) * NS + s;
        As[c][s] = g_A[o];
        Es[c][s] = g_E[o];
    }
    __syncthreads();

    float h = 0.f;
    #pragma unroll
    for (int c = 0; c < NCHUNK; c++) {
        g_hin[(b * NCHUNK + c) * NS + s] = h;
        h = fmaf(As[c][s], h, Es[c][s]);
    }
}

// Pass 3: replay each chunk from its entry state, write tf32 states.
// __ldcs on g_a/g_b (dead after this), normal store on g_hs (reused 32x).
__global__ void __launch_bounds__(256)
scan3_kernel() {
    const int t  = threadIdx.x;
    const int c  = blockIdx.x * 16 + (t >> 4);
    const int b  = blockIdx.y;
    const int s  = (t & 15) * 4;
    int o = (b * NCHUNK + c) * NS + s;
    float4 h = *(const float4*)&g_hin[o];
    size_t base = ((size_t)b * NT + (size_t)c * CLEN) * NS + s;
    #pragma unroll 8
    for (int tt = 0; tt < CLEN; tt++) {
        size_t idx = base + (size_t)tt * NS;
        float4 av = __ldcs((const float4*)&g_a[idx]);
        float4 bv = __ldcs((const float4*)&g_b[idx]);
        h.x = fmaf(av.x, h.x, bv.x);
        h.y = fmaf(av.y, h.y, bv.y);
        h.z = fmaf(av.z, h.z, bv.z);
        h.w = fmaf(av.w, h.w, bv.w);
        uint4 u = make_uint4(f2tf(h.x), f2tf(h.y), f2tf(h.z), f2tf(h.w));
        *(uint4*)&g_hs[idx] = u;
    }
}

// ---------------- kernel 3: out = x + hs @ Wout^T + bout ------------------
// GEMM M=32768, N=2048, K=64. BM=128, BN=64 tiles (K one smem shot).
// 8 warps in 4(m) x 2(n) grid, warp tile 32x32. 52.5KB smem -> 4 CTA/SM.
#define LDK3 68   // 68 mod 32 = 4 -> conflict-free frags

__global__ void __launch_bounds__(256, 4)
out_kernel(const float* __restrict__ x, const float* __restrict__ bout,
           float* __restrict__ out) {
    extern __shared__ char sm[];
    unsigned int* Hs = (unsigned int*)sm;                     // [128][LDK3]
    unsigned int* Ws = (unsigned int*)(sm + 128*LDK3*4);      // [64][LDK3]
    float*        bs = (float*)(sm + 192*LDK3*4);             // [64]

    const int tid  = threadIdx.x;
    const int warp = tid >> 5, lane = tid & 31;
    const int g  = lane >> 2, t4 = lane & 3;
    const int wm = warp >> 1, wn = warp & 1;
    const int n0 = blockIdx.x * 64;
    const int m0 = blockIdx.y * 128;

    if (tid < 64) bs[tid] = bout[n0 + tid];

    #pragma unroll
    for (int j = 0; j < 8; j++) {            // Hs: 2048 chunks of 16B
        int c   = tid + j * 256;
        int row = c >> 4;                    // 16 chunks per 64-wide row
        int kc  = (c & 15) * 4;
        cpa16(&Hs[row*LDK3 + kc], &g_hs[(size_t)(m0 + row)*NS + kc]);
    }
    #pragma unroll
    for (int j = 0; j < 4; j++) {            // Ws: 1024 chunks of 16B
        int c   = tid + j * 256;
        int row = c >> 4;
        int kc  = (c & 15) * 4;
        cpa16(&Ws[row*LDK3 + kc], &g_Wo[(size_t)(n0 + row)*NS + kc]);
    }
    cp_commit();
    asm volatile("cp.async.wait_group 0;" ::: "memory");
    __syncthreads();

    float acc[2][4][4];
    #pragma unroll
    for (int i = 0; i < 2; i++)
        #pragma unroll
        for (int j = 0; j < 4; j++)
            #pragma unroll
            for (int k = 0; k < 4; k++) acc[i][j][k] = 0.f;

    #pragma unroll
    for (int kk = 0; kk < 8; kk++) {
        unsigned int af[2][4];
        #pragma unroll
        for (int im = 0; im < 2; im++) {
            int r = wm*32 + im*16 + g;
            int c = kk*8 + t4;
            af[im][0] = Hs[r*LDK3 + c];
            af[im][1] = Hs[(r+8)*LDK3 + c];
            af[im][2] = Hs[r*LDK3 + c + 4];
            af[im][3] = Hs[(r+8)*LDK3 + c + 4];
        }
        unsigned int bf[4][2];
        #pragma unroll
        for (int in = 0; in < 4; in++) {
            int n = wn*32 + in*8 + g;
            int c = kk*8 + t4;
            bf[in][0] = Ws[n*LDK3 + c];
            bf[in][1] = Ws[n*LDK3 + c + 4];
        }
        #pragma unroll
        for (int im = 0; im < 2; im++)
            #pragma unroll
            for (int in = 0; in < 4; in++)
                mma8(acc[im][in], af[im], bf[in]);
    }

    // Epilogue: + x (residual, streaming load) + bout, streaming store
    #pragma unroll
    for (int im = 0; im < 2; im++) {
        #pragma unroll
        for (int in = 0; in < 4; in++) {
            int dl = wn*32 + in*8 + 2*t4;        // local col (0..63)
            int d  = n0 + dl;
            float bo0 = bs[dl], bo1 = bs[dl + 1];
            size_t r0 = (size_t)(m0 + wm*32 + im*16 + g);
            float2 x0 = __ldcs((const float2*)&x[r0*ND + d]);
            float2 x1 = __ldcs((const float2*)&x[(r0+8)*ND + d]);
            float2 o0 = make_float2(acc[im][in][0] + x0.x + bo0,
                                    acc[im][in][1] + x0.y + bo1);
            float2 o1 = make_float2(acc[im][in][2] + x1.x + bo0,
                                    acc[im][in][3] + x1.y + bo1);
            __stcs((float2*)&out[r0*ND + d],     o0);
            __stcs((float2*)&out[(r0+8)*ND + d], o1);
        }
    }
}

// ---------------- launcher ------------------------------------------------
extern "C" void kernel_launch(void* const* d_in, const int* in_sizes, int n_in,
                              void* d_out, int out_size) {
    const float* x    = (const float*)d_in[0];
    const float* Wa   = (const float*)d_in[1];
    const float* ba   = (const float*)d_in[2];
    const float* Wb   = (const float*)d_in[3];
    const float* bb   = (const float*)d_in[4];
    const float* Wout = (const float*)d_in[5];
    const float* bout = (const float*)d_in[6];
    float* out = (float*)d_out;
    (void)in_sizes; (void)n_in; (void)out_size;

    const size_t sm1 = (size_t)2*NSTG*128*LDA1*4 + 512;  // 111104 B
    const size_t sm3 = (size_t)192*LDK3*4 + 256;         // 52480 B
    cudaFuncSetAttribute(proj_kernel, cudaFuncAttributeMaxDynamicSharedMemorySize,
                         (int)sm1);
    cudaFuncSetAttribute(out_kernel, cudaFuncAttributeMaxDynamicSharedMemorySize,
                         (int)sm3);

    // 0. convert weights to tf32 scratch
    const int prep_elems = N_CAT*ND + ND*NS;         // 393216
    prep_kernel<<<(prep_elems + 255) / 256, 256>>>(Wa, Wb, Wout);

    // 1. projections + tanh (3-stage pipeline)
    proj_kernel<<<M_TOT / 128, 512, sm1>>>(x, ba, bb);

    // 2. chunked affine recurrence scan (3 phases)
    scan1_kernel<<<dim3(NCHUNK/16, NB), 256>>>();
    scan2_kernel<<<NB, 64>>>();
    scan3_kernel<<<dim3(NCHUNK/16, NB), 256>>>();

    // 3. output projection + residual
    out_kernel<<<dim3(ND / 64, M_TOT / 128), 256, sm3>>>(x, bout, out);
}

// round 9
// speedup vs baseline: 1.1176x; 1.1176x over previous
#include <cuda_runtime.h>

// Problem constants
#define NB 8
#define NT 4096
#define ND 2048
#define NS 64
#define M_TOT (NB*NT)      // 32768 rows
#define N_CAT (2*NS)       // 128 (Wa rows ++ Wb rows)
#define NCHUNK 64          // scan chunks
#define CLEN   64          // steps per chunk (NCHUNK*CLEN == NT)

// ---------------- scratch (static __device__ — no allocations allowed) ----
__device__ float        g_a[(size_t)M_TOT*NS];        // 8 MB  gate  (fp32)
__device__ float        g_b[(size_t)M_TOT*NS];        // 8 MB  input (fp32)
__device__ unsigned int g_hs[(size_t)M_TOT*NS];       // 8 MB  states (tf32 bits)
__device__ float        g_A[(size_t)NB*NCHUNK*NS];    // chunk gate products
__device__ float        g_E[(size_t)NB*NCHUNK*NS];    // chunk local end values
__device__ float        g_hin[(size_t)NB*NCHUNK*NS];  // chunk entry states

// ---------------- helpers -------------------------------------------------
__device__ __forceinline__ unsigned int f2tf(float f) {
    unsigned int u;
    asm("cvt.rna.tf32.f32 %0, %1;" : "=r"(u) : "f"(f));
    return u;
}

__device__ __forceinline__ void mma8(float c[4], const unsigned int a[4],
                                     const unsigned int b[2]) {
    asm volatile(
        "mma.sync.aligned.m16n8k8.row.col.f32.tf32.tf32.f32 "
        "{%0,%1,%2,%3},{%4,%5,%6,%7},{%8,%9},{%0,%1,%2,%3};"
        : "+f"(c[0]), "+f"(c[1]), "+f"(c[2]), "+f"(c[3])
        : "r"(a[0]), "r"(a[1]), "r"(a[2]), "r"(a[3]), "r"(b[0]), "r"(b[1]));
}

__device__ __forceinline__ void cpa16(void* sdst, const void* gsrc) {
    unsigned int sa = (unsigned int)__cvta_generic_to_shared(sdst);
    asm volatile("cp.async.cg.shared.global [%0], [%1], 16;"
                 :: "r"(sa), "l"(gsrc) : "memory");
}
__device__ __forceinline__ void cp_commit() {
    asm volatile("cp.async.commit_group;" ::: "memory");
}

// ---------------- kernel 1: a,b = tanh(x @ [Wa;Wb]^T + bias) --------------
// GEMM M=32768, N=128, K=2048. 128x128 blocks, BK=32 double-buffered.
// 8 warps in 2(m) x 4(n) grid, warp tile 64x32 (cuts W-side LDS 2x).
// Weights cp.async'd directly from Wa/Wb (fp32 bits fed to tf32 mma -> HW
// truncation, same as the X side).
#define BK1  32
#define LDA1 36   // padded smem stride (36 mod 32 = 4 -> conflict-free frags)

__global__ void __launch_bounds__(256, 2)
proj_kernel(const float* __restrict__ x,
            const float* __restrict__ Wa, const float* __restrict__ Wb,
            const float* __restrict__ ba, const float* __restrict__ bb) {
    extern __shared__ char sm[];
    float*        Xs   = (float*)sm;                          // [2][128][LDA1]
    float*        Ws   = (float*)(sm + 2*128*LDA1*4);         // [2][128][LDA1]
    float*        bias = (float*)(sm + 4*128*LDA1*4);         // [128]

    const int tid  = threadIdx.x;
    const int warp = tid >> 5, lane = tid & 31;
    const int g  = lane >> 2, t4 = lane & 3;
    const int wm = warp >> 2, wn = warp & 3;   // 2m x 4n, warp tile 64x32
    const int m0 = blockIdx.x * 128;

    if (tid < 128) bias[tid] = (tid < NS) ? ba[tid] : bb[tid - NS];

    float acc[4][4][4];
    #pragma unroll
    for (int i = 0; i < 4; i++)
        #pragma unroll
        for (int j = 0; j < 4; j++)
            #pragma unroll
            for (int k = 0; k < 4; k++) acc[i][j][k] = 0.f;

    auto issue = [&](int buf, int k0) {
        #pragma unroll
        for (int j = 0; j < 4; j++) {
            int c   = tid + j * 256;       // 1024 chunks of 4 floats
            int row = c >> 3;              // 8 chunks per 32-wide row
            int kc  = (c & 7) * 4;
            cpa16(&Xs[(buf*128 + row)*LDA1 + kc],
                  &x[(size_t)(m0 + row)*ND + k0 + kc]);
            const float* wsrc = (row < NS)
                ? &Wa[(size_t)row*ND + k0 + kc]
                : &Wb[(size_t)(row - NS)*ND + k0 + kc];
            cpa16(&Ws[(buf*128 + row)*LDA1 + kc], wsrc);
        }
        cp_commit();
    };

    issue(0, 0);
    const int KT = ND / BK1;   // 64
    for (int kt = 0; kt < KT; kt++) {
        const int cur = kt & 1;
        if (kt + 1 < KT) {
            issue(cur ^ 1, (kt + 1) * BK1);
            asm volatile("cp.async.wait_group 1;" ::: "memory");
        } else {
            asm volatile("cp.async.wait_group 0;" ::: "memory");
        }
        __syncthreads();

        const float* Xc = &Xs[cur * 128 * LDA1];
        const float* Wc = &Ws[cur * 128 * LDA1];
        #pragma unroll
        for (int kk = 0; kk < 4; kk++) {
            unsigned int af[4][4];
            #pragma unroll
            for (int im = 0; im < 4; im++) {
                int r = wm*64 + im*16 + g;
                int c = kk*8 + t4;
                // raw fp32 bits: tensor core truncates mantissa to tf32
                af[im][0] = __float_as_uint(Xc[r*LDA1 + c]);
                af[im][1] = __float_as_uint(Xc[(r+8)*LDA1 + c]);
                af[im][2] = __float_as_uint(Xc[r*LDA1 + c + 4]);
                af[im][3] = __float_as_uint(Xc[(r+8)*LDA1 + c + 4]);
            }
            unsigned int bf[4][2];
            #pragma unroll
            for (int in = 0; in < 4; in++) {
                int n = wn*32 + in*8 + g;
                int c = kk*8 + t4;
                bf[in][0] = __float_as_uint(Wc[n*LDA1 + c]);
                bf[in][1] = __float_as_uint(Wc[n*LDA1 + c + 4]);
            }
            #pragma unroll
            for (int im = 0; im < 4; im++)
                #pragma unroll
                for (int in = 0; in < 4; in++)
                    mma8(acc[im][in], af[im], bf[in]);
        }
        __syncthreads();
    }

    // Epilogue: + bias, tanh, split store to g_a (cols<64) / g_b (cols>=64)
    float* dst = (wn >= 2) ? g_b : g_a;
    #pragma unroll
    for (int im = 0; im < 4; im++) {
        #pragma unroll
        for (int in = 0; in < 4; in++) {
            int ncol = wn*32 + in*8 + 2*t4;       // global col 0..127
            float b0v = bias[ncol], b1v = bias[ncol + 1];
            int cl = (wn & 1)*32 + in*8 + 2*t4;   // local col within 64
            size_t r0 = (size_t)(m0 + wm*64 + im*16 + g);
            float2 v0 = make_float2(tanhf(acc[im][in][0] + b0v),
                                    tanhf(acc[im][in][1] + b1v));
            float2 v1 = make_float2(tanhf(acc[im][in][2] + b0v),
                                    tanhf(acc[im][in][3] + b1v));
            *(float2*)&dst[r0*NS + cl]       = v0;
            *(float2*)&dst[(r0+8)*NS + cl]   = v1;
        }
    }
}

// ---------------- kernel 2: chunked affine scan over T --------------------
// Pass 1: per (batch, chunk, state): A = prod(a), E = local scan end (h_in=0)
__global__ void __launch_bounds__(32)
scan1_kernel() {
    const int c = blockIdx.x, b = blockIdx.y;
    const int s = threadIdx.x * 2;
    size_t base = ((size_t)b * NT + (size_t)c * CLEN) * NS + s;
    float2 A = make_float2(1.f, 1.f), E = make_float2(0.f, 0.f);
    #pragma unroll 16
    for (int t = 0; t < CLEN; t++) {
        float2 av = *(const float2*)&g_a[base + (size_t)t * NS];
        float2 bv = *(const float2*)&g_b[base + (size_t)t * NS];
        E.x = fmaf(av.x, E.x, bv.x);
        E.y = fmaf(av.y, E.y, bv.y);
        A.x *= av.x;
        A.y *= av.y;
    }
    int o = (b * NCHUNK + c) * NS + s;
    *(float2*)&g_A[o] = A;
    *(float2*)&g_E[o] = E;
}

// Pass 2: sequential combine across chunks, staged through shared memory.
__global__ void __launch_bounds__(64)
scan2_kernel() {
    __shared__ float As[NCHUNK][NS];
    __shared__ float Es[NCHUNK][NS];
    const int b = blockIdx.x, s = threadIdx.x;

    #pragma unroll
    for (int c = 0; c < NCHUNK; c++) {
        int o = (b * NCHUNK + c) * NS + s;
        As[c][s] = g_A[o];
        Es[c][s] = g_E[o];
    }
    __syncthreads();

    float h = 0.f;
    #pragma unroll
    for (int c = 0; c < NCHUNK; c++) {
        g_hin[(b * NCHUNK + c) * NS + s] = h;
        h = fmaf(As[c][s], h, Es[c][s]);
    }
}

// Pass 3: replay each chunk from its entry state, write tf32 states.
__global__ void __launch_bounds__(32)
scan3_kernel() {
    const int c = blockIdx.x, b = blockIdx.y;
    const int s = threadIdx.x * 2;
    int o = (b * NCHUNK + c) * NS + s;
    float2 h = *(const float2*)&g_hin[o];
    size_t base = ((size_t)b * NT + (size_t)c * CLEN) * NS + s;
    #pragma unroll 16
    for (int t = 0; t < CLEN; t++) {
        size_t idx = base + (size_t)t * NS;
        float2 av = __ldcs((const float2*)&g_a[idx]);
        float2 bv = __ldcs((const float2*)&g_b[idx]);
        h.x = fmaf(av.x, h.x, bv.x);
        h.y = fmaf(av.y, h.y, bv.y);
        uint2 u = make_uint2(f2tf(h.x), f2tf(h.y));
        *(uint2*)&g_hs[idx] = u;
    }
}

// ---------------- kernel 3: out = x + hs @ Wout^T + bout ------------------
// GEMM M=32768, N=2048, K=64. BM=128, BN=64 tiles (K one smem shot).
// 8 warps in 4(m) x 2(n) grid, warp tile 32x32. 52.5KB smem -> 4 CTA/SM.
// Wout [D][S] row-major is exactly the [n][k] layout the B tile needs.
#define LDK3 68   // 68 mod 32 = 4 -> conflict-free frags

__global__ void __launch_bounds__(256, 4)
out_kernel(const float* __restrict__ x, const float* __restrict__ Wout,
           const float* __restrict__ bout, float* __restrict__ out) {
    extern __shared__ char sm[];
    unsigned int* Hs = (unsigned int*)sm;                     // [128][LDK3]
    float*        Ws = (float*)(sm + 128*LDK3*4);             // [64][LDK3]
    float*        bs = (float*)(sm + 192*LDK3*4);             // [64]

    const int tid  = threadIdx.x;
    const int warp = tid >> 5, lane = tid & 31;
    const int g  = lane >> 2, t4 = lane & 3;
    const int wm = warp >> 1, wn = warp & 1;
    const int n0 = blockIdx.x * 64;
    const int m0 = blockIdx.y * 128;

    if (tid < 64) bs[tid] = bout[n0 + tid];

    #pragma unroll
    for (int j = 0; j < 8; j++) {            // Hs: 2048 chunks of 16B
        int c   = tid + j * 256;
        int row = c >> 4;                    // 16 chunks per 64-wide row
        int kc  = (c & 15) * 4;
        cpa16(&Hs[row*LDK3 + kc], &g_hs[(size_t)(m0 + row)*NS + kc]);
    }
    #pragma unroll
    for (int j = 0; j < 4; j++) {            // Ws: 1024 chunks of 16B
        int c   = tid + j * 256;
        int row = c >> 4;
        int kc  = (c & 15) * 4;
        cpa16(&Ws[row*LDK3 + kc], &Wout[(size_t)(n0 + row)*NS + kc]);
    }
    cp_commit();
    asm volatile("cp.async.wait_group 0;" ::: "memory");
    __syncthreads();

    float acc[2][4][4];
    #pragma unroll
    for (int i = 0; i < 2; i++)
        #pragma unroll
        for (int j = 0; j < 4; j++)
            #pragma unroll
            for (int k = 0; k < 4; k++) acc[i][j][k] = 0.f;

    #pragma unroll
    for (int kk = 0; kk < 8; kk++) {
        unsigned int af[2][4];
        #pragma unroll
        for (int im = 0; im < 2; im++) {
            int r = wm*32 + im*16 + g;
            int c = kk*8 + t4;
            af[im][0] = Hs[r*LDK3 + c];
            af[im][1] = Hs[(r+8)*LDK3 + c];
            af[im][2] = Hs[r*LDK3 + c + 4];
            af[im][3] = Hs[(r+8)*LDK3 + c + 4];
        }
        unsigned int bf[4][2];
        #pragma unroll
        for (int in = 0; in < 4; in++) {
            int n = wn*32 + in*8 + g;
            int c = kk*8 + t4;
            bf[in][0] = __float_as_uint(Ws[n*LDK3 + c]);
            bf[in][1] = __float_as_uint(Ws[n*LDK3 + c + 4]);
        }
        #pragma unroll
        for (int im = 0; im < 2; im++)
            #pragma unroll
            for (int in = 0; in < 4; in++)
                mma8(acc[im][in], af[im], bf[in]);
    }

    // Epilogue: + x (residual, streaming load) + bout, streaming store
    #pragma unroll
    for (int im = 0; im < 2; im++) {
        #pragma unroll
        for (int in = 0; in < 4; in++) {
            int dl = wn*32 + in*8 + 2*t4;        // local col (0..63)
            int d  = n0 + dl;
            float bo0 = bs[dl], bo1 = bs[dl + 1];
            size_t r0 = (size_t)(m0 + wm*32 + im*16 + g);
            float2 x0 = __ldcs((const float2*)&x[r0*ND + d]);
            float2 x1 = __ldcs((const float2*)&x[(r0+8)*ND + d]);
            float2 o0 = make_float2(acc[im][in][0] + x0.x + bo0,
                                    acc[im][in][1] + x0.y + bo1);
            float2 o1 = make_float2(acc[im][in][2] + x1.x + bo0,
                                    acc[im][in][3] + x1.y + bo1);
            __stcs((float2*)&out[r0*ND + d],     o0);
            __stcs((float2*)&out[(r0+8)*ND + d], o1);
        }
    }
}

// ---------------- launcher ------------------------------------------------
extern "C" void kernel_launch(void* const* d_in, const int* in_sizes, int n_in,
                              void* d_out, int out_size) {
    const float* x    = (const float*)d_in[0];
    const float* Wa   = (const float*)d_in[1];
    const float* ba   = (const float*)d_in[2];
    const float* Wb   = (const float*)d_in[3];
    const float* bb   = (const float*)d_in[4];
    const float* Wout = (const float*)d_in[5];
    const float* bout = (const float*)d_in[6];
    float* out = (float*)d_out;
    (void)in_sizes; (void)n_in; (void)out_size;

    const size_t sm1 = (size_t)4*128*LDA1*4 + 512;   // 74240 B
    const size_t sm3 = (size_t)192*LDK3*4 + 256;     // 52480 B
    cudaFuncSetAttribute(proj_kernel, cudaFuncAttributeMaxDynamicSharedMemorySize,
                         (int)sm1);
    cudaFuncSetAttribute(out_kernel, cudaFuncAttributeMaxDynamicSharedMemorySize,
                         (int)sm3);

    // 1. projections + tanh (weights consumed directly, no prep pass)
    proj_kernel<<<M_TOT / 128, 256, sm1>>>(x, Wa, Wb, ba, bb);

    // 2. chunked affine recurrence scan (3 phases)
    scan1_kernel<<<dim3(NCHUNK, NB), 32>>>();
    scan2_kernel<<<NB, 64>>>();
    scan3_kernel<<<dim3(NCHUNK, NB), 32>>>();

    // 3. output projection + residual
    out_kernel<<<dim3(ND / 64, M_TOT / 128), 256, sm3>>>(x, Wout, bout, out);
}

// round 10
// speedup vs baseline: 1.1398x; 1.0199x over previous
#include <cuda_runtime.h>

// Problem constants
#define NB 8
#define NT 4096
#define ND 2048
#define NS 64
#define M_TOT (NB*NT)      // 32768 rows
#define N_CAT (2*NS)       // 128 (Wa rows ++ Wb rows)
#define NCHUNK 64          // scan chunks
#define CLEN   64          // steps per chunk (NCHUNK*CLEN == NT)

// ---------------- scratch (static __device__ — no allocations allowed) ----
__device__ float        g_a[(size_t)M_TOT*NS];        // 8 MB  gate  (fp32)
__device__ float        g_b[(size_t)M_TOT*NS];        // 8 MB  input (fp32)
__device__ unsigned int g_hs[(size_t)M_TOT*NS];       // 8 MB  states (tf32 bits)
__device__ float        g_A[(size_t)NB*NCHUNK*NS];    // chunk gate products
__device__ float        g_E[(size_t)NB*NCHUNK*NS];    // chunk local end values
__device__ float        g_hin[(size_t)NB*NCHUNK*NS];  // chunk entry states

// ---------------- helpers -------------------------------------------------
__device__ __forceinline__ unsigned int f2tf(float f) {
    unsigned int u;
    asm("cvt.rna.tf32.f32 %0, %1;" : "=r"(u) : "f"(f));
    return u;
}

__device__ __forceinline__ void mma8(float c[4], const unsigned int a[4],
                                     const unsigned int b[2]) {
    asm volatile(
        "mma.sync.aligned.m16n8k8.row.col.f32.tf32.tf32.f32 "
        "{%0,%1,%2,%3},{%4,%5,%6,%7},{%8,%9},{%0,%1,%2,%3};"
        : "+f"(c[0]), "+f"(c[1]), "+f"(c[2]), "+f"(c[3])
        : "r"(a[0]), "r"(a[1]), "r"(a[2]), "r"(a[3]), "r"(b[0]), "r"(b[1]));
}

__device__ __forceinline__ void cpa16(void* sdst, const void* gsrc) {
    unsigned int sa = (unsigned int)__cvta_generic_to_shared(sdst);
    asm volatile("cp.async.cg.shared.global [%0], [%1], 16;"
                 :: "r"(sa), "l"(gsrc) : "memory");
}
__device__ __forceinline__ void cp_commit() {
    asm volatile("cp.async.commit_group;" ::: "memory");
}

// ---------------- kernel 1: a,b = tanh(x @ [Wa;Wb]^T + bias) --------------
// GEMM M=32768, N=128, K=2048. 128x128 blocks, BK=32 double-buffered.
// 8 warps in 2(m) x 4(n) grid, warp tile 64x32 (cuts W-side LDS 2x).
#define BK1  32
#define LDA1 36   // padded smem stride (36 mod 32 = 4 -> conflict-free frags)

__global__ void __launch_bounds__(256, 2)
proj_kernel(const float* __restrict__ x,
            const float* __restrict__ Wa, const float* __restrict__ Wb,
            const float* __restrict__ ba, const float* __restrict__ bb) {
    extern __shared__ char sm[];
    float*        Xs   = (float*)sm;                          // [2][128][LDA1]
    float*        Ws   = (float*)(sm + 2*128*LDA1*4);         // [2][128][LDA1]
    float*        bias = (float*)(sm + 4*128*LDA1*4);         // [128]

    const int tid  = threadIdx.x;
    const int warp = tid >> 5, lane = tid & 31;
    const int g  = lane >> 2, t4 = lane & 3;
    const int wm = warp >> 2, wn = warp & 3;   // 2m x 4n, warp tile 64x32
    const int m0 = blockIdx.x * 128;

    if (tid < 128) bias[tid] = (tid < NS) ? ba[tid] : bb[tid - NS];

    float acc[4][4][4];
    #pragma unroll
    for (int i = 0; i < 4; i++)
        #pragma unroll
        for (int j = 0; j < 4; j++)
            #pragma unroll
            for (int k = 0; k < 4; k++) acc[i][j][k] = 0.f;

    auto issue = [&](int buf, int k0) {
        #pragma unroll
        for (int j = 0; j < 4; j++) {
            int c   = tid + j * 256;       // 1024 chunks of 4 floats
            int row = c >> 3;              // 8 chunks per 32-wide row
            int kc  = (c & 7) * 4;
            cpa16(&Xs[(buf*128 + row)*LDA1 + kc],
                  &x[(size_t)(m0 + row)*ND + k0 + kc]);
            const float* wsrc = (row < NS)
                ? &Wa[(size_t)row*ND + k0 + kc]
                : &Wb[(size_t)(row - NS)*ND + k0 + kc];
            cpa16(&Ws[(buf*128 + row)*LDA1 + kc], wsrc);
        }
        cp_commit();
    };

    issue(0, 0);
    const int KT = ND / BK1;   // 64
    for (int kt = 0; kt < KT; kt++) {
        const int cur = kt & 1;
        if (kt + 1 < KT) {
            issue(cur ^ 1, (kt + 1) * BK1);
            asm volatile("cp.async.wait_group 1;" ::: "memory");
        } else {
            asm volatile("cp.async.wait_group 0;" ::: "memory");
        }
        __syncthreads();

        const float* Xc = &Xs[cur * 128 * LDA1];
        const float* Wc = &Ws[cur * 128 * LDA1];
        #pragma unroll
        for (int kk = 0; kk < 4; kk++) {
            unsigned int af[4][4];
            #pragma unroll
            for (int im = 0; im < 4; im++) {
                int r = wm*64 + im*16 + g;
                int c = kk*8 + t4;
                // raw fp32 bits: tensor core truncates mantissa to tf32
                af[im][0] = __float_as_uint(Xc[r*LDA1 + c]);
                af[im][1] = __float_as_uint(Xc[(r+8)*LDA1 + c]);
                af[im][2] = __float_as_uint(Xc[r*LDA1 + c + 4]);
                af[im][3] = __float_as_uint(Xc[(r+8)*LDA1 + c + 4]);
            }
            unsigned int bf[4][2];
            #pragma unroll
            for (int in = 0; in < 4; in++) {
                int n = wn*32 + in*8 + g;
                int c = kk*8 + t4;
                bf[in][0] = __float_as_uint(Wc[n*LDA1 + c]);
                bf[in][1] = __float_as_uint(Wc[n*LDA1 + c + 4]);
            }
            #pragma unroll
            for (int im = 0; im < 4; im++)
                #pragma unroll
                for (int in = 0; in < 4; in++)
                    mma8(acc[im][in], af[im], bf[in]);
        }
        __syncthreads();
    }

    // Epilogue: + bias, tanh, split store to g_a (cols<64) / g_b (cols>=64)
    float* dst = (wn >= 2) ? g_b : g_a;
    #pragma unroll
    for (int im = 0; im < 4; im++) {
        #pragma unroll
        for (int in = 0; in < 4; in++) {
            int ncol = wn*32 + in*8 + 2*t4;       // global col 0..127
            float b0v = bias[ncol], b1v = bias[ncol + 1];
            int cl = (wn & 1)*32 + in*8 + 2*t4;   // local col within 64
            size_t r0 = (size_t)(m0 + wm*64 + im*16 + g);
            float2 v0 = make_float2(tanhf(acc[im][in][0] + b0v),
                                    tanhf(acc[im][in][1] + b1v));
            float2 v1 = make_float2(tanhf(acc[im][in][2] + b0v),
                                    tanhf(acc[im][in][3] + b1v));
            *(float2*)&dst[r0*NS + cl]       = v0;
            *(float2*)&dst[(r0+8)*NS + cl]   = v1;
        }
    }
}

// ---------------- kernel 2: chunked affine scan over T --------------------
// Pass 1: per (batch, chunk): stage the chunk's contiguous 32KB (a,b) slab
// into smem with cp.async (pure-bandwidth, deep MLP), then 64 threads run
// the per-state chain entirely out of conflict-free LDS.
__global__ void __launch_bounds__(256)
scan1_kernel() {
    __shared__ float As[CLEN*NS];   // 16 KB
    __shared__ float Bs[CLEN*NS];   // 16 KB
    const int c = blockIdx.x, b = blockIdx.y;
    size_t base = ((size_t)b * NT + (size_t)c * CLEN) * NS;

    #pragma unroll
    for (int j = 0; j < 4; j++) {
        int idx = (threadIdx.x + j * 256) * 4;   // 4096 floats per array
        cpa16(&As[idx], &g_a[base + idx]);
        cpa16(&Bs[idx], &g_b[base + idx]);
    }
    cp_commit();
    asm volatile("cp.async.wait_group 0;" ::: "memory");
    __syncthreads();

    if (threadIdx.x < NS) {
        const int s = threadIdx.x;
        float A = 1.f, E = 0.f;
        #pragma unroll 16
        for (int t = 0; t < CLEN; t++) {
            float av = As[t*NS + s];
            float bv = Bs[t*NS + s];
            E = fmaf(av, E, bv);
            A *= av;
        }
        int o = (b * NCHUNK + c) * NS + s;
        g_A[o] = A;
        g_E[o] = E;
    }
}

// Pass 2: sequential combine across chunks, staged through shared memory.
__global__ void __launch_bounds__(64)
scan2_kernel() {
    __shared__ float As[NCHUNK][NS];
    __shared__ float Es[NCHUNK][NS];
    const int b = blockIdx.x, s = threadIdx.x;

    #pragma unroll
    for (int c = 0; c < NCHUNK; c++) {
        int o = (b * NCHUNK + c) * NS + s;
        As[c][s] = g_A[o];
        Es[c][s] = g_E[o];
    }
    __syncthreads();

    float h = 0.f;
    #pragma unroll
    for (int c = 0; c < NCHUNK; c++) {
        g_hin[(b * NCHUNK + c) * NS + s] = h;
        h = fmaf(As[c][s], h, Es[c][s]);
    }
}

// Pass 3: replay each chunk from its entry state out of LDS, write tf32
// states coalesced (256B per step from 64 lanes).
__global__ void __launch_bounds__(256)
scan3_kernel() {
    __shared__ float As[CLEN*NS];   // 16 KB
    __shared__ float Bs[CLEN*NS];   // 16 KB
    const int c = blockIdx.x, b = blockIdx.y;
    size_t base = ((size_t)b * NT + (size_t)c * CLEN) * NS;

    #pragma unroll
    for (int j = 0; j < 4; j++) {
        int idx = (threadIdx.x + j * 256) * 4;
        cpa16(&As[idx], &g_a[base + idx]);
        cpa16(&Bs[idx], &g_b[base + idx]);
    }
    cp_commit();
    asm volatile("cp.async.wait_group 0;" ::: "memory");
    __syncthreads();

    if (threadIdx.x < NS) {
        const int s = threadIdx.x;
        float h = g_hin[(b * NCHUNK + c) * NS + s];
        #pragma unroll 16
        for (int t = 0; t < CLEN; t++) {
            float av = As[t*NS + s];
            float bv = Bs[t*NS + s];
            h = fmaf(av, h, bv);
            g_hs[base + t*NS + s] = f2tf(h);
        }
    }
}

// ---------------- kernel 3: out = x + hs @ Wout^T + bout ------------------
// GEMM M=32768, N=2048, K=64. BM=128, BN=64 tiles (K one smem shot).
// 8 warps in 4(m) x 2(n) grid, warp tile 32x32. 52.5KB smem -> 4 CTA/SM.
// Wout [D][S] row-major is exactly the [n][k] layout the B tile needs.
#define LDK3 68   // 68 mod 32 = 4 -> conflict-free frags

__global__ void __launch_bounds__(256, 4)
out_kernel(const float* __restrict__ x, const float* __restrict__ Wout,
           const float* __restrict__ bout, float* __restrict__ out) {
    extern __shared__ char sm[];
    unsigned int* Hs = (unsigned int*)sm;                     // [128][LDK3]
    float*        Ws = (float*)(sm + 128*LDK3*4);             // [64][LDK3]
    float*        bs = (float*)(sm + 192*LDK3*4);             // [64]

    const int tid  = threadIdx.x;
    const int warp = tid >> 5, lane = tid & 31;
    const int g  = lane >> 2, t4 = lane & 3;
    const int wm = warp >> 1, wn = warp & 1;
    const int n0 = blockIdx.x * 64;
    const int m0 = blockIdx.y * 128;

    if (tid < 64) bs[tid] = bout[n0 + tid];

    #pragma unroll
    for (int j = 0; j < 8; j++) {            // Hs: 2048 chunks of 16B
        int c   = tid + j * 256;
        int row = c >> 4;                    // 16 chunks per 64-wide row
        int kc  = (c & 15) * 4;
        cpa16(&Hs[row*LDK3 + kc], &g_hs[(size_t)(m0 + row)*NS + kc]);
    }
    #pragma unroll
    for (int j = 0; j < 4; j++) {            // Ws: 1024 chunks of 16B
        int c   = tid + j * 256;
        int row = c >> 4;
        int kc  = (c & 15) * 4;
        cpa16(&Ws[row*LDK3 + kc], &Wout[(size_t)(n0 + row)*NS + kc]);
    }
    cp_commit();
    asm volatile("cp.async.wait_group 0;" ::: "memory");
    __syncthreads();

    float acc[2][4][4];
    #pragma unroll
    for (int i = 0; i < 2; i++)
        #pragma unroll
        for (int j = 0; j < 4; j++)
            #pragma unroll
            for (int k = 0; k < 4; k++) acc[i][j][k] = 0.f;

    #pragma unroll
    for (int kk = 0; kk < 8; kk++) {
        unsigned int af[2][4];
        #pragma unroll
        for (int im = 0; im < 2; im++) {
            int r = wm*32 + im*16 + g;
            int c = kk*8 + t4;
            af[im][0] = Hs[r*LDK3 + c];
            af[im][1] = Hs[(r+8)*LDK3 + c];
            af[im][2] = Hs[r*LDK3 + c + 4];
            af[im][3] = Hs[(r+8)*LDK3 + c + 4];
        }
        unsigned int bf[4][2];
        #pragma unroll
        for (int in = 0; in < 4; in++) {
            int n = wn*32 + in*8 + g;
            int c = kk*8 + t4;
            bf[in][0] = __float_as_uint(Ws[n*LDK3 + c]);
            bf[in][1] = __float_as_uint(Ws[n*LDK3 + c + 4]);
        }
        #pragma unroll
        for (int im = 0; im < 2; im++)
            #pragma unroll
            for (int in = 0; in < 4; in++)
                mma8(acc[im][in], af[im], bf[in]);
    }

    // Epilogue: + x (residual, streaming load) + bout, streaming store
    #pragma unroll
    for (int im = 0; im < 2; im++) {
        #pragma unroll
        for (int in = 0; in < 4; in++) {
            int dl = wn*32 + in*8 + 2*t4;        // local col (0..63)
            int d  = n0 + dl;
            float bo0 = bs[dl], bo1 = bs[dl + 1];
            size_t r0 = (size_t)(m0 + wm*32 + im*16 + g);
            float2 x0 = __ldcs((const float2*)&x[r0*ND + d]);
            float2 x1 = __ldcs((const float2*)&x[(r0+8)*ND + d]);
            float2 o0 = make_float2(acc[im][in][0] + x0.x + bo0,
                                    acc[im][in][1] + x0.y + bo1);
            float2 o1 = make_float2(acc[im][in][2] + x1.x + bo0,
                                    acc[im][in][3] + x1.y + bo1);
            __stcs((float2*)&out[r0*ND + d],     o0);
            __stcs((float2*)&out[(r0+8)*ND + d], o1);
        }
    }
}

// ---------------- launcher ------------------------------------------------
extern "C" void kernel_launch(void* const* d_in, const int* in_sizes, int n_in,
                              void* d_out, int out_size) {
    const float* x    = (const float*)d_in[0];
    const float* Wa   = (const float*)d_in[1];
    const float* ba   = (const float*)d_in[2];
    const float* Wb   = (const float*)d_in[3];
    const float* bb   = (const float*)d_in[4];
    const float* Wout = (const float*)d_in[5];
    const float* bout = (const float*)d_in[6];
    float* out = (float*)d_out;
    (void)in_sizes; (void)n_in; (void)out_size;

    const size_t sm1 = (size_t)4*128*LDA1*4 + 512;   // 74240 B
    const size_t sm3 = (size_t)192*LDK3*4 + 256;     // 52480 B
    cudaFuncSetAttribute(proj_kernel, cudaFuncAttributeMaxDynamicSharedMemorySize,
                         (int)sm1);
    cudaFuncSetAttribute(out_kernel, cudaFuncAttributeMaxDynamicSharedMemorySize,
                         (int)sm3);

    // 1. projections + tanh (weights consumed directly, no prep pass)
    proj_kernel<<<M_TOT / 128, 256, sm1>>>(x, Wa, Wb, ba, bb);

    // 2. chunked affine recurrence scan (3 phases, smem-staged chains)
    scan1_kernel<<<dim3(NCHUNK, NB), 256>>>();
    scan2_kernel<<<NB, 64>>>();
    scan3_kernel<<<dim3(NCHUNK, NB), 256>>>();

    // 3. output projection + residual
    out_kernel<<<dim3(ND / 64, M_TOT / 128), 256, sm3>>>(x, Wout, bout, out);
}

// round 11
// speedup vs baseline: 1.2896x; 1.1315x over previous
#include <cuda_runtime.h>
#include <cuda_fp16.h>

// Problem constants
#define NB 8
#define NT 4096
#define ND 2048
#define NS 64
#define M_TOT (NB*NT)      // 32768 rows
#define N_CAT (2*NS)       // 128 (Wa rows ++ Wb rows)
#define NCHUNK 64          // scan chunks
#define CLEN   64          // steps per chunk (NCHUNK*CLEN == NT)

// ---------------- scratch (static __device__ — no allocations allowed) ----
__device__ float        g_a[(size_t)M_TOT*NS];        // 8 MB  gate  (fp32)
__device__ float        g_b[(size_t)M_TOT*NS];        // 8 MB  input (fp32)
__device__ unsigned int g_hs[(size_t)M_TOT*NS];       // 8 MB  states (tf32 bits)
__device__ float        g_A[(size_t)NB*NCHUNK*NS];    // chunk gate products
__device__ float        g_E[(size_t)NB*NCHUNK*NS];    // chunk local end values
__device__ float        g_hin[(size_t)NB*NCHUNK*NS];  // chunk entry states

// ---------------- helpers -------------------------------------------------
__device__ __forceinline__ unsigned int f2tf(float f) {
    unsigned int u;
    asm("cvt.rna.tf32.f32 %0, %1;" : "=r"(u) : "f"(f));
    return u;
}

// tf32 m16n8k8 (used by out_kernel)
__device__ __forceinline__ void mma8(float c[4], const unsigned int a[4],
                                     const unsigned int b[2]) {
    asm volatile(
        "mma.sync.aligned.m16n8k8.row.col.f32.tf32.tf32.f32 "
        "{%0,%1,%2,%3},{%4,%5,%6,%7},{%8,%9},{%0,%1,%2,%3};"
        : "+f"(c[0]), "+f"(c[1]), "+f"(c[2]), "+f"(c[3])
        : "r"(a[0]), "r"(a[1]), "r"(a[2]), "r"(a[3]), "r"(b[0]), "r"(b[1]));
}

// fp16 m16n8k16 (used by proj_kernel) — 2x the legacy tf32 rate, same
// 10-bit mantissa.
__device__ __forceinline__ void mma16h(float c[4], const unsigned int a[4],
                                       const unsigned int b[2]) {
    asm volatile(
        "mma.sync.aligned.m16n8k16.row.col.f32.f16.f16.f32 "
        "{%0,%1,%2,%3},{%4,%5,%6,%7},{%8,%9},{%0,%1,%2,%3};"
        : "+f"(c[0]), "+f"(c[1]), "+f"(c[2]), "+f"(c[3])
        : "r"(a[0]), "r"(a[1]), "r"(a[2]), "r"(a[3]), "r"(b[0]), "r"(b[1]));
}

__device__ __forceinline__ unsigned int pack_h2(float lo, float hi) {
    __half2 h = __floats2half2_rn(lo, hi);
    return *reinterpret_cast<unsigned int*>(&h);
}

__device__ __forceinline__ void cpa16(void* sdst, const void* gsrc) {
    unsigned int sa = (unsigned int)__cvta_generic_to_shared(sdst);
    asm volatile("cp.async.cg.shared.global [%0], [%1], 16;"
                 :: "r"(sa), "l"(gsrc) : "memory");
}
__device__ __forceinline__ void cp_commit() {
    asm volatile("cp.async.commit_group;" ::: "memory");
}

// ---------------- kernel 1: a,b = tanh(x @ [Wa;Wb]^T + bias) --------------
// GEMM M=32768, N=128, K=2048. 128x128 blocks, BK=32 double-buffered.
// 8 warps in 2(m) x 4(n) grid, warp tile 64x32, fp16 m16n8k16 mma.
// smem holds fp32 (cp.async direct); fragments converted to half2 at load.
// LDA1=40: row stride = 8 banks -> conflict-free 8-byte fragment loads.
#define BK1  32
#define LDA1 40

__global__ void __launch_bounds__(256, 2)
proj_kernel(const float* __restrict__ x,
            const float* __restrict__ Wa, const float* __restrict__ Wb,
            const float* __restrict__ ba, const float* __restrict__ bb) {
    extern __shared__ char sm[];
    float*        Xs   = (float*)sm;                          // [2][128][LDA1]
    float*        Ws   = (float*)(sm + 2*128*LDA1*4);         // [2][128][LDA1]
    float*        bias = (float*)(sm + 4*128*LDA1*4);         // [128]

    const int tid  = threadIdx.x;
    const int warp = tid >> 5, lane = tid & 31;
    const int g  = lane >> 2, t4 = lane & 3;
    const int wm = warp >> 2, wn = warp & 3;   // 2m x 4n, warp tile 64x32
    const int m0 = blockIdx.x * 128;

    if (tid < 128) bias[tid] = (tid < NS) ? ba[tid] : bb[tid - NS];

    float acc[4][4][4];
    #pragma unroll
    for (int i = 0; i < 4; i++)
        #pragma unroll
        for (int j = 0; j < 4; j++)
            #pragma unroll
            for (int k = 0; k < 4; k++) acc[i][j][k] = 0.f;

    auto issue = [&](int buf, int k0) {
        #pragma unroll
        for (int j = 0; j < 4; j++) {
            int c   = tid + j * 256;       // 1024 chunks of 4 floats
            int row = c >> 3;              // 8 chunks per 32-wide row
            int kc  = (c & 7) * 4;
            cpa16(&Xs[(buf*128 + row)*LDA1 + kc],
                  &x[(size_t)(m0 + row)*ND + k0 + kc]);
            const float* wsrc = (row < NS)
                ? &Wa[(size_t)row*ND + k0 + kc]
                : &Wb[(size_t)(row - NS)*ND + k0 + kc];
            cpa16(&Ws[(buf*128 + row)*LDA1 + kc], wsrc);
        }
        cp_commit();
    };

    issue(0, 0);
    const int KT = ND / BK1;   // 64
    for (int kt = 0; kt < KT; kt++) {
        const int cur = kt & 1;
        if (kt + 1 < KT) {
            issue(cur ^ 1, (kt + 1) * BK1);
            asm volatile("cp.async.wait_group 1;" ::: "memory");
        } else {
            asm volatile("cp.async.wait_group 0;" ::: "memory");
        }
        __syncthreads();

        const float* Xc = &Xs[cur * 128 * LDA1];
        const float* Wc = &Ws[cur * 128 * LDA1];
        #pragma unroll
        for (int kk = 0; kk < 2; kk++) {       // two K=16 steps per BK=32
            const int cb = kk*16 + 2*t4;
            unsigned int af[4][4];
            #pragma unroll
            for (int im = 0; im < 4; im++) {
                int r = wm*64 + im*16 + g;
                float2 p0 = *(const float2*)&Xc[r*LDA1 + cb];
                float2 p1 = *(const float2*)&Xc[(r+8)*LDA1 + cb];
                float2 p2 = *(const float2*)&Xc[r*LDA1 + cb + 8];
                float2 p3 = *(const float2*)&Xc[(r+8)*LDA1 + cb + 8];
                af[im][0] = pack_h2(p0.x, p0.y);
                af[im][1] = pack_h2(p1.x, p1.y);
                af[im][2] = pack_h2(p2.x, p2.y);
                af[im][3] = pack_h2(p3.x, p3.y);
            }
            unsigned int bf[4][2];
            #pragma unroll
            for (int in = 0; in < 4; in++) {
                int n = wn*32 + in*8 + g;
                float2 q0 = *(const float2*)&Wc[n*LDA1 + cb];
                float2 q1 = *(const float2*)&Wc[n*LDA1 + cb + 8];
                bf[in][0] = pack_h2(q0.x, q0.y);
                bf[in][1] = pack_h2(q1.x, q1.y);
            }
            #pragma unroll
            for (int im = 0; im < 4; im++)
                #pragma unroll
                for (int in = 0; in < 4; in++)
                    mma16h(acc[im][in], af[im], bf[in]);
        }
        __syncthreads();
    }

    // Epilogue: + bias, tanh, split store to g_a (cols<64) / g_b (cols>=64)
    float* dst = (wn >= 2) ? g_b : g_a;
    #pragma unroll
    for (int im = 0; im < 4; im++) {
        #pragma unroll
        for (int in = 0; in < 4; in++) {
            int ncol = wn*32 + in*8 + 2*t4;       // global col 0..127
            float b0v = bias[ncol], b1v = bias[ncol + 1];
            int cl = (wn & 1)*32 + in*8 + 2*t4;   // local col within 64
            size_t r0 = (size_t)(m0 + wm*64 + im*16 + g);
            float2 v0 = make_float2(tanhf(acc[im][in][0] + b0v),
                                    tanhf(acc[im][in][1] + b1v));
            float2 v1 = make_float2(tanhf(acc[im][in][2] + b0v),
                                    tanhf(acc[im][in][3] + b1v));
            *(float2*)&dst[r0*NS + cl]       = v0;
            *(float2*)&dst[(r0+8)*NS + cl]   = v1;
        }
    }
}

// ---------------- kernel 2: chunked affine scan over T --------------------
// Pass 1: stage chunk's contiguous 32KB (a,b) slab into smem via cp.async,
// then 64 threads run the chain out of conflict-free LDS.
__global__ void __launch_bounds__(256)
scan1_kernel() {
    __shared__ float As[CLEN*NS];   // 16 KB
    __shared__ float Bs[CLEN*NS];   // 16 KB
    const int c = blockIdx.x, b = blockIdx.y;
    size_t base = ((size_t)b * NT + (size_t)c * CLEN) * NS;

    #pragma unroll
    for (int j = 0; j < 4; j++) {
        int idx = (threadIdx.x + j * 256) * 4;   // 4096 floats per array
        cpa16(&As[idx], &g_a[base + idx]);
        cpa16(&Bs[idx], &g_b[base + idx]);
    }
    cp_commit();
    asm volatile("cp.async.wait_group 0;" ::: "memory");
    __syncthreads();

    if (threadIdx.x < NS) {
        const int s = threadIdx.x;
        float A = 1.f, E = 0.f;
        #pragma unroll 16
        for (int t = 0; t < CLEN; t++) {
            float av = As[t*NS + s];
            float bv = Bs[t*NS + s];
            E = fmaf(av, E, bv);
            A *= av;
        }
        int o = (b * NCHUNK + c) * NS + s;
        g_A[o] = A;
        g_E[o] = E;
    }
}

// Pass 2: sequential combine across chunks, staged through shared memory.
__global__ void __launch_bounds__(64)
scan2_kernel() {
    __shared__ float As[NCHUNK][NS];
    __shared__ float Es[NCHUNK][NS];
    const int b = blockIdx.x, s = threadIdx.x;

    #pragma unroll
    for (int c = 0; c < NCHUNK; c++) {
        int o = (b * NCHUNK + c) * NS + s;
        As[c][s] = g_A[o];
        Es[c][s] = g_E[o];
    }
    __syncthreads();

    float h = 0.f;
    #pragma unroll
    for (int c = 0; c < NCHUNK; c++) {
        g_hin[(b * NCHUNK + c) * NS + s] = h;
        h = fmaf(As[c][s], h, Es[c][s]);
    }
}

// Pass 3: replay each chunk from its entry state out of LDS, write tf32
// states coalesced.
__global__ void __launch_bounds__(256)
scan3_kernel() {
    __shared__ float As[CLEN*NS];   // 16 KB
    __shared__ float Bs[CLEN*NS];   // 16 KB
    const int c = blockIdx.x, b = blockIdx.y;
    size_t base = ((size_t)b * NT + (size_t)c * CLEN) * NS;

    #pragma unroll
    for (int j = 0; j < 4; j++) {
        int idx = (threadIdx.x + j * 256) * 4;
        cpa16(&As[idx], &g_a[base + idx]);
        cpa16(&Bs[idx], &g_b[base + idx]);
    }
    cp_commit();
    asm volatile("cp.async.wait_group 0;" ::: "memory");
    __syncthreads();

    if (threadIdx.x < NS) {
        const int s = threadIdx.x;
        float h = g_hin[(b * NCHUNK + c) * NS + s];
        #pragma unroll 16
        for (int t = 0; t < CLEN; t++) {
            float av = As[t*NS + s];
            float bv = Bs[t*NS + s];
            h = fmaf(av, h, bv);
            g_hs[base + t*NS + s] = f2tf(h);
        }
    }
}

// ---------------- kernel 3: out = x + hs @ Wout^T + bout ------------------
// GEMM M=32768, N=2048, K=64. BM=128, BN=64 tiles (K one smem shot).
// 8 warps in 4(m) x 2(n) grid, warp tile 32x32 tf32. 52.5KB smem, 4 CTA/SM.
#define LDK3 68   // 68 mod 32 = 4 -> conflict-free frags

__global__ void __launch_bounds__(256, 4)
out_kernel(const float* __restrict__ x, const float* __restrict__ Wout,
           const float* __restrict__ bout, float* __restrict__ out) {
    extern __shared__ char sm[];
    unsigned int* Hs = (unsigned int*)sm;                     // [128][LDK3]
    float*        Ws = (float*)(sm + 128*LDK3*4);             // [64][LDK3]
    float*        bs = (float*)(sm + 192*LDK3*4);             // [64]

    const int tid  = threadIdx.x;
    const int warp = tid >> 5, lane = tid & 31;
    const int g  = lane >> 2, t4 = lane & 3;
    const int wm = warp >> 1, wn = warp & 1;
    const int n0 = blockIdx.x * 64;
    const int m0 = blockIdx.y * 128;

    if (tid < 64) bs[tid] = bout[n0 + tid];

    #pragma unroll
    for (int j = 0; j < 8; j++) {            // Hs: 2048 chunks of 16B
        int c   = tid + j * 256;
        int row = c >> 4;                    // 16 chunks per 64-wide row
        int kc  = (c & 15) * 4;
        cpa16(&Hs[row*LDK3 + kc], &g_hs[(size_t)(m0 + row)*NS + kc]);
    }
    #pragma unroll
    for (int j = 0; j < 4; j++) {            // Ws: 1024 chunks of 16B
        int c   = tid + j * 256;
        int row = c >> 4;
        int kc  = (c & 15) * 4;
        cpa16(&Ws[row*LDK3 + kc], &Wout[(size_t)(n0 + row)*NS + kc]);
    }
    cp_commit();
    asm volatile("cp.async.wait_group 0;" ::: "memory");
    __syncthreads();

    float acc[2][4][4];
    #pragma unroll
    for (int i = 0; i < 2; i++)
        #pragma unroll
        for (int j = 0; j < 4; j++)
            #pragma unroll
            for (int k = 0; k < 4; k++) acc[i][j][k] = 0.f;

    #pragma unroll
    for (int kk = 0; kk < 8; kk++) {
        unsigned int af[2][4];
        #pragma unroll
        for (int im = 0; im < 2; im++) {
            int r = wm*32 + im*16 + g;
            int c = kk*8 + t4;
            af[im][0] = Hs[r*LDK3 + c];
            af[im][1] = Hs[(r+8)*LDK3 + c];
            af[im][2] = Hs[r*LDK3 + c + 4];
            af[im][3] = Hs[(r+8)*LDK3 + c + 4];
        }
        unsigned int bf[4][2];
        #pragma unroll
        for (int in = 0; in < 4; in++) {
            int n = wn*32 + in*8 + g;
            int c = kk*8 + t4;
            bf[in][0] = __float_as_uint(Ws[n*LDK3 + c]);
            bf[in][1] = __float_as_uint(Ws[n*LDK3 + c + 4]);
        }
        #pragma unroll
        for (int im = 0; im < 2; im++)
            #pragma unroll
            for (int in = 0; in < 4; in++)
                mma8(acc[im][in], af[im], bf[in]);
    }

    // Epilogue: + x (residual, streaming load) + bout, streaming store
    #pragma unroll
    for (int im = 0; im < 2; im++) {
        #pragma unroll
        for (int in = 0; in < 4; in++) {
            int dl = wn*32 + in*8 + 2*t4;        // local col (0..63)
            int d  = n0 + dl;
            float bo0 = bs[dl], bo1 = bs[dl + 1];
            size_t r0 = (size_t)(m0 + wm*32 + im*16 + g);
            float2 x0 = __ldcs((const float2*)&x[r0*ND + d]);
            float2 x1 = __ldcs((const float2*)&x[(r0+8)*ND + d]);
            float2 o0 = make_float2(acc[im][in][0] + x0.x + bo0,
                                    acc[im][in][1] + x0.y + bo1);
            float2 o1 = make_float2(acc[im][in][2] + x1.x + bo0,
                                    acc[im][in][3] + x1.y + bo1);
            __stcs((float2*)&out[r0*ND + d],     o0);
            __stcs((float2*)&out[(r0+8)*ND + d], o1);
        }
    }
}

// ---------------- launcher ------------------------------------------------
extern "C" void kernel_launch(void* const* d_in, const int* in_sizes, int n_in,
                              void* d_out, int out_size) {
    const float* x    = (const float*)d_in[0];
    const float* Wa   = (const float*)d_in[1];
    const float* ba   = (const float*)d_in[2];
    const float* Wb   = (const float*)d_in[3];
    const float* bb   = (const float*)d_in[4];
    const float* Wout = (const float*)d_in[5];
    const float* bout = (const float*)d_in[6];
    float* out = (float*)d_out;
    (void)in_sizes; (void)n_in; (void)out_size;

    const size_t sm1 = (size_t)4*128*LDA1*4 + 512;   // 82432 B
    const size_t sm3 = (size_t)192*LDK3*4 + 256;     // 52480 B
    cudaFuncSetAttribute(proj_kernel, cudaFuncAttributeMaxDynamicSharedMemorySize,
                         (int)sm1);
    cudaFuncSetAttribute(out_kernel, cudaFuncAttributeMaxDynamicSharedMemorySize,
                         (int)sm3);

    // 1. projections + tanh (fp16 tensor path, weights consumed directly)
    proj_kernel<<<M_TOT / 128, 256, sm1>>>(x, Wa, Wb, ba, bb);

    // 2. chunked affine recurrence scan (3 phases, smem-staged chains)
    scan1_kernel<<<dim3(NCHUNK, NB), 256>>>();
    scan2_kernel<<<NB, 64>>>();
    scan3_kernel<<<dim3(NCHUNK, NB), 256>>>();

    // 3. output projection + residual
    out_kernel<<<dim3(ND / 64, M_TOT / 128), 256, sm3>>>(x, Wout, bout, out);
}

// round 12
// speedup vs baseline: 1.5891x; 1.2322x over previous
#include <cuda_runtime.h>
#include <cuda_fp16.h>

// Problem constants
#define NB 8
#define NT 4096
#define ND 2048
#define NS 64
#define M_TOT (NB*NT)      // 32768 rows
#define N_CAT (2*NS)       // 128 (Wa rows ++ Wb rows)
#define NCHUNK 64          // scan chunks
#define CLEN   64          // steps per chunk (NCHUNK*CLEN == NT)

// ---------------- scratch (static __device__ — no allocations allowed) ----
__device__ float        g_a[(size_t)M_TOT*NS];        // 8 MB  gate  (fp32)
__device__ float        g_b[(size_t)M_TOT*NS];        // 8 MB  input (fp32)
__device__ __half       g_hs[(size_t)M_TOT*NS];       // 4 MB  states (fp16)
__device__ float        g_A[(size_t)NB*NCHUNK*NS];    // chunk gate products
__device__ float        g_E[(size_t)NB*NCHUNK*NS];    // chunk local end values
__device__ float        g_hin[(size_t)NB*NCHUNK*NS];  // chunk entry states

// ---------------- helpers -------------------------------------------------
// fp16 m16n8k16 — 2x the legacy tf32 rate, same 10-bit mantissa.
__device__ __forceinline__ void mma16h(float c[4], const unsigned int a[4],
                                       const unsigned int b[2]) {
    asm volatile(
        "mma.sync.aligned.m16n8k16.row.col.f32.f16.f16.f32 "
        "{%0,%1,%2,%3},{%4,%5,%6,%7},{%8,%9},{%0,%1,%2,%3};"
        : "+f"(c[0]), "+f"(c[1]), "+f"(c[2]), "+f"(c[3])
        : "r"(a[0]), "r"(a[1]), "r"(a[2]), "r"(a[3]), "r"(b[0]), "r"(b[1]));
}

__device__ __forceinline__ unsigned int pack_h2(float lo, float hi) {
    __half2 h = __floats2half2_rn(lo, hi);
    return *reinterpret_cast<unsigned int*>(&h);
}

__device__ __forceinline__ void cpa16(void* sdst, const void* gsrc) {
    unsigned int sa = (unsigned int)__cvta_generic_to_shared(sdst);
    asm volatile("cp.async.cg.shared.global [%0], [%1], 16;"
                 :: "r"(sa), "l"(gsrc) : "memory");
}
__device__ __forceinline__ void cp_commit() {
    asm volatile("cp.async.commit_group;" ::: "memory");
}

// ---------------- kernel 1: a,b = tanh(x @ [Wa;Wb]^T + bias) --------------
// GEMM M=32768, N=128, K=2048. 128x128 blocks, BK=32 double-buffered.
// 8 warps in 2(m) x 4(n) grid, warp tile 64x32, fp16 m16n8k16 mma.
#define BK1  32
#define LDA1 40

__global__ void __launch_bounds__(256, 2)
proj_kernel(const float* __restrict__ x,
            const float* __restrict__ Wa, const float* __restrict__ Wb,
            const float* __restrict__ ba, const float* __restrict__ bb) {
    extern __shared__ char sm[];
    float*        Xs   = (float*)sm;                          // [2][128][LDA1]
    float*        Ws   = (float*)(sm + 2*128*LDA1*4);         // [2][128][LDA1]
    float*        bias = (float*)(sm + 4*128*LDA1*4);         // [128]

    const int tid  = threadIdx.x;
    const int warp = tid >> 5, lane = tid & 31;
    const int g  = lane >> 2, t4 = lane & 3;
    const int wm = warp >> 2, wn = warp & 3;   // 2m x 4n, warp tile 64x32
    const int m0 = blockIdx.x * 128;

    if (tid < 128) bias[tid] = (tid < NS) ? ba[tid] : bb[tid - NS];

    float acc[4][4][4];
    #pragma unroll
    for (int i = 0; i < 4; i++)
        #pragma unroll
        for (int j = 0; j < 4; j++)
            #pragma unroll
            for (int k = 0; k < 4; k++) acc[i][j][k] = 0.f;

    auto issue = [&](int buf, int k0) {
        #pragma unroll
        for (int j = 0; j < 4; j++) {
            int c   = tid + j * 256;       // 1024 chunks of 4 floats
            int row = c >> 3;              // 8 chunks per 32-wide row
            int kc  = (c & 7) * 4;
            cpa16(&Xs[(buf*128 + row)*LDA1 + kc],
                  &x[(size_t)(m0 + row)*ND + k0 + kc]);
            const float* wsrc = (row < NS)
                ? &Wa[(size_t)row*ND + k0 + kc]
                : &Wb[(size_t)(row - NS)*ND + k0 + kc];
            cpa16(&Ws[(buf*128 + row)*LDA1 + kc], wsrc);
        }
        cp_commit();
    };

    issue(0, 0);
    const int KT = ND / BK1;   // 64
    for (int kt = 0; kt < KT; kt++) {
        const int cur = kt & 1;
        if (kt + 1 < KT) {
            issue(cur ^ 1, (kt + 1) * BK1);
            asm volatile("cp.async.wait_group 1;" ::: "memory");
        } else {
            asm volatile("cp.async.wait_group 0;" ::: "memory");
        }
        __syncthreads();

        const float* Xc = &Xs[cur * 128 * LDA1];
        const float* Wc = &Ws[cur * 128 * LDA1];
        #pragma unroll
        for (int kk = 0; kk < 2; kk++) {       // two K=16 steps per BK=32
            const int cb = kk*16 + 2*t4;
            unsigned int af[4][4];
            #pragma unroll
            for (int im = 0; im < 4; im++) {
                int r = wm*64 + im*16 + g;
                float2 p0 = *(const float2*)&Xc[r*LDA1 + cb];
                float2 p1 = *(const float2*)&Xc[(r+8)*LDA1 + cb];
                float2 p2 = *(const float2*)&Xc[r*LDA1 + cb + 8];
                float2 p3 = *(const float2*)&Xc[(r+8)*LDA1 + cb + 8];
                af[im][0] = pack_h2(p0.x, p0.y);
                af[im][1] = pack_h2(p1.x, p1.y);
                af[im][2] = pack_h2(p2.x, p2.y);
                af[im][3] = pack_h2(p3.x, p3.y);
            }
            unsigned int bf[4][2];
            #pragma unroll
            for (int in = 0; in < 4; in++) {
                int n = wn*32 + in*8 + g;
                float2 q0 = *(const float2*)&Wc[n*LDA1 + cb];
                float2 q1 = *(const float2*)&Wc[n*LDA1 + cb + 8];
                bf[in][0] = pack_h2(q0.x, q0.y);
                bf[in][1] = pack_h2(q1.x, q1.y);
            }
            #pragma unroll
            for (int im = 0; im < 4; im++)
                #pragma unroll
                for (int in = 0; in < 4; in++)
                    mma16h(acc[im][in], af[im], bf[in]);
        }
        __syncthreads();
    }

    // Epilogue: + bias, tanh, split store to g_a (cols<64) / g_b (cols>=64)
    float* dst = (wn >= 2) ? g_b : g_a;
    #pragma unroll
    for (int im = 0; im < 4; im++) {
        #pragma unroll
        for (int in = 0; in < 4; in++) {
            int ncol = wn*32 + in*8 + 2*t4;       // global col 0..127
            float b0v = bias[ncol], b1v = bias[ncol + 1];
            int cl = (wn & 1)*32 + in*8 + 2*t4;   // local col within 64
            size_t r0 = (size_t)(m0 + wm*64 + im*16 + g);
            float2 v0 = make_float2(tanhf(acc[im][in][0] + b0v),
                                    tanhf(acc[im][in][1] + b1v));
            float2 v1 = make_float2(tanhf(acc[im][in][2] + b0v),
                                    tanhf(acc[im][in][3] + b1v));
            *(float2*)&dst[r0*NS + cl]       = v0;
            *(float2*)&dst[(r0+8)*NS + cl]   = v1;
        }
    }
}

// ---------------- kernel 2: chunked affine scan over T --------------------
// Pass 1: stage chunk's contiguous 32KB (a,b) slab into smem via cp.async,
// then 64 threads run the chain out of conflict-free LDS.
__global__ void __launch_bounds__(256)
scan1_kernel() {
    __shared__ float As[CLEN*NS];   // 16 KB
    __shared__ float Bs[CLEN*NS];   // 16 KB
    const int c = blockIdx.x, b = blockIdx.y;
    size_t base = ((size_t)b * NT + (size_t)c * CLEN) * NS;

    #pragma unroll
    for (int j = 0; j < 4; j++) {
        int idx = (threadIdx.x + j * 256) * 4;   // 4096 floats per array
        cpa16(&As[idx], &g_a[base + idx]);
        cpa16(&Bs[idx], &g_b[base + idx]);
    }
    cp_commit();
    asm volatile("cp.async.wait_group 0;" ::: "memory");
    __syncthreads();

    if (threadIdx.x < NS) {
        const int s = threadIdx.x;
        float A = 1.f, E = 0.f;
        #pragma unroll 16
        for (int t = 0; t < CLEN; t++) {
            float av = As[t*NS + s];
            float bv = Bs[t*NS + s];
            E = fmaf(av, E, bv);
            A *= av;
        }
        int o = (b * NCHUNK + c) * NS + s;
        g_A[o] = A;
        g_E[o] = E;
    }
}

// Pass 2: sequential combine across chunks, staged through shared memory.
__global__ void __launch_bounds__(64)
scan2_kernel() {
    __shared__ float As[NCHUNK][NS];
    __shared__ float Es[NCHUNK][NS];
    const int b = blockIdx.x, s = threadIdx.x;

    #pragma unroll
    for (int c = 0; c < NCHUNK; c++) {
        int o = (b * NCHUNK + c) * NS + s;
        As[c][s] = g_A[o];
        Es[c][s] = g_E[o];
    }
    __syncthreads();

    float h = 0.f;
    #pragma unroll
    for (int c = 0; c < NCHUNK; c++) {
        g_hin[(b * NCHUNK + c) * NS + s] = h;
        h = fmaf(As[c][s], h, Es[c][s]);
    }
}

// Pass 3: replay each chunk from its entry state out of LDS; 32 lanes own
// 2 states each (float2 smem loads, half2 coalesced stores -> 4 MB total).
__global__ void __launch_bounds__(256)
scan3_kernel() {
    __shared__ float As[CLEN*NS];   // 16 KB
    __shared__ float Bs[CLEN*NS];   // 16 KB
    const int c = blockIdx.x, b = blockIdx.y;
    size_t base = ((size_t)b * NT + (size_t)c * CLEN) * NS;

    #pragma unroll
    for (int j = 0; j < 4; j++) {
        int idx = (threadIdx.x + j * 256) * 4;
        cpa16(&As[idx], &g_a[base + idx]);
        cpa16(&Bs[idx], &g_b[base + idx]);
    }
    cp_commit();
    asm volatile("cp.async.wait_group 0;" ::: "memory");
    __syncthreads();

    if (threadIdx.x < 32) {
        const int s = threadIdx.x * 2;
        float2 h = *(const float2*)&g_hin[(b * NCHUNK + c) * NS + s];
        #pragma unroll 16
        for (int t = 0; t < CLEN; t++) {
            float2 av = *(const float2*)&As[t*NS + s];
            float2 bv = *(const float2*)&Bs[t*NS + s];
            h.x = fmaf(av.x, h.x, bv.x);
            h.y = fmaf(av.y, h.y, bv.y);
            *(__half2*)&g_hs[base + t*NS + s] = __floats2half2_rn(h.x, h.y);
        }
    }
}

// ---------------- kernel 3: out = x + hs @ Wout^T + bout ------------------
// GEMM M=32768, N=2048, K=64, fp16 m16n8k16 (hs fp16, Wout packed at load).
// BM=128, BN=64; 8 warps in 4(m) x 2(n), warp tile 32x32. ~37KB smem.
#define LDH3 72   // half stride: 144B row -> 36-bank stride, conflict-free
#define LDW3 72   // float stride: 8-bank stride mod 32, conflict-free f2 loads

__global__ void __launch_bounds__(256, 4)
out_kernel(const float* __restrict__ x, const float* __restrict__ Wout,
           const float* __restrict__ bout, float* __restrict__ out) {
    extern __shared__ char sm[];
    __half* Hs = (__half*)sm;                                 // [128][LDH3]
    float*  Ws = (float*)(sm + 128*LDH3*2);                   // [64][LDW3]
    float*  bs = (float*)(sm + 128*LDH3*2 + 64*LDW3*4);       // [64]

    const int tid  = threadIdx.x;
    const int warp = tid >> 5, lane = tid & 31;
    const int g  = lane >> 2, t4 = lane & 3;
    const int wm = warp >> 1, wn = warp & 1;
    const int n0 = blockIdx.x * 64;
    const int m0 = blockIdx.y * 128;

    if (tid < 64) bs[tid] = bout[n0 + tid];

    #pragma unroll
    for (int j = 0; j < 4; j++) {            // Hs: 1024 chunks of 8 halves
        int c   = tid + j * 256;
        int row = c >> 3;                    // 8 chunks per 64-half row
        int kc  = (c & 7) * 8;
        cpa16(&Hs[row*LDH3 + kc], &g_hs[(size_t)(m0 + row)*NS + kc]);
    }
    #pragma unroll
    for (int j = 0; j < 4; j++) {            // Ws: 1024 chunks of 4 floats
        int c   = tid + j * 256;
        int row = c >> 4;
        int kc  = (c & 15) * 4;
        cpa16(&Ws[row*LDW3 + kc], &Wout[(size_t)(n0 + row)*NS + kc]);
    }
    cp_commit();
    asm volatile("cp.async.wait_group 0;" ::: "memory");
    __syncthreads();

    float acc[2][4][4];
    #pragma unroll
    for (int i = 0; i < 2; i++)
        #pragma unroll
        for (int j = 0; j < 4; j++)
            #pragma unroll
            for (int k = 0; k < 4; k++) acc[i][j][k] = 0.f;

    #pragma unroll
    for (int kk = 0; kk < 4; kk++) {         // four K=16 steps
        const int cb = kk*16 + 2*t4;
        unsigned int af[2][4];
        #pragma unroll
        for (int im = 0; im < 2; im++) {
            int r = wm*32 + im*16 + g;
            af[im][0] = *(const unsigned int*)&Hs[r*LDH3 + cb];
            af[im][1] = *(const unsigned int*)&Hs[(r+8)*LDH3 + cb];
            af[im][2] = *(const unsigned int*)&Hs[r*LDH3 + cb + 8];
            af[im][3] = *(const unsigned int*)&Hs[(r+8)*LDH3 + cb + 8];
        }
        unsigned int bf[4][2];
        #pragma unroll
        for (int in = 0; in < 4; in++) {
            int n = wn*32 + in*8 + g;
            float2 q0 = *(const float2*)&Ws[n*LDW3 + cb];
            float2 q1 = *(const float2*)&Ws[n*LDW3 + cb + 8];
            bf[in][0] = pack_h2(q0.x, q0.y);
            bf[in][1] = pack_h2(q1.x, q1.y);
        }
        #pragma unroll
        for (int im = 0; im < 2; im++)
            #pragma unroll
            for (int in = 0; in < 4; in++)
                mma16h(acc[im][in], af[im], bf[in]);
    }

    // Epilogue: + x (residual, streaming load) + bout, streaming store
    #pragma unroll
    for (int im = 0; im < 2; im++) {
        #pragma unroll
        for (int in = 0; in < 4; in++) {
            int dl = wn*32 + in*8 + 2*t4;        // local col (0..63)
            int d  = n0 + dl;
            float bo0 = bs[dl], bo1 = bs[dl + 1];
            size_t r0 = (size_t)(m0 + wm*32 + im*16 + g);
            float2 x0 = __ldcs((const float2*)&x[r0*ND + d]);
            float2 x1 = __ldcs((const float2*)&x[(r0+8)*ND + d]);
            float2 o0 = make_float2(acc[im][in][0] + x0.x + bo0,
                                    acc[im][in][1] + x0.y + bo1);
            float2 o1 = make_float2(acc[im][in][2] + x1.x + bo0,
                                    acc[im][in][3] + x1.y + bo1);
            __stcs((float2*)&out[r0*ND + d],     o0);
            __stcs((float2*)&out[(r0+8)*ND + d], o1);
        }
    }
}

// ---------------- launcher ------------------------------------------------
extern "C" void kernel_launch(void* const* d_in, const int* in_sizes, int n_in,
                              void* d_out, int out_size) {
    const float* x    = (const float*)d_in[0];
    const float* Wa   = (const float*)d_in[1];
    const float* ba   = (const float*)d_in[2];
    const float* Wb   = (const float*)d_in[3];
    const float* bb   = (const float*)d_in[4];
    const float* Wout = (const float*)d_in[5];
    const float* bout = (const float*)d_in[6];
    float* out = (float*)d_out;
    (void)in_sizes; (void)n_in; (void)out_size;

    const size_t sm1 = (size_t)4*128*LDA1*4 + 512;               // 82432 B
    const size_t sm3 = (size_t)128*LDH3*2 + 64*LDW3*4 + 256;     // 37120 B
    cudaFuncSetAttribute(proj_kernel, cudaFuncAttributeMaxDynamicSharedMemorySize,
                         (int)sm1);
    cudaFuncSetAttribute(out_kernel, cudaFuncAttributeMaxDynamicSharedMemorySize,
                         (int)sm3);

    // 1. projections + tanh (fp16 tensor path, weights consumed directly)
    proj_kernel<<<M_TOT / 128, 256, sm1>>>(x, Wa, Wb, ba, bb);

    // 2. chunked affine recurrence scan (3 phases, smem-staged chains)
    scan1_kernel<<<dim3(NCHUNK, NB), 256>>>();
    scan2_kernel<<<NB, 64>>>();
    scan3_kernel<<<dim3(NCHUNK, NB), 256>>>();

    // 3. output projection + residual (fp16 tensor path)
    out_kernel<<<dim3(ND / 64, M_TOT / 128), 256, sm3>>>(x, Wout, bout, out);
}